// round 6
// baseline (speedup 1.0000x reference)
#include <cuda_runtime.h>
#include <cuda_bf16.h>
#include <cstdint>

// Problem constants (fixed by the dataset)
#define B_SZ   1024
#define NIN    2048
#define NOUT   2048
#define NC     10
#define TSTEPS 10

#define DECAY  0.2f
#define THRESH 0.5f
#define TD     0.1f   // THRESH * DECAY

// Scratch: h = x @ W_enc^T  (8 MB) and per-row loss partials.
__device__ float g_h[B_SZ * NOUT];
__device__ float g_lossPartial[B_SZ];

// ---------------------------------------------------------------------------
// Packed fp32x2 helpers (Blackwell: fma.rn.f32x2 — 2 IEEE fp32 FMAs per issue)
// ---------------------------------------------------------------------------
__device__ __forceinline__ unsigned long long pack2(float lo, float hi) {
    unsigned long long d;
    asm("mov.b64 %0, {%1, %2};" : "=l"(d)
        : "r"(__float_as_int(lo)), "r"(__float_as_int(hi)));
    return d;
}
__device__ __forceinline__ void unpack2(unsigned long long v, float& lo, float& hi) {
    int a, b;
    asm("mov.b64 {%0, %1}, %2;" : "=r"(a), "=r"(b) : "l"(v));
    lo = __int_as_float(a); hi = __int_as_float(b);
}
__device__ __forceinline__ unsigned long long ffma2(unsigned long long a,
                                                    unsigned long long b,
                                                    unsigned long long c) {
    unsigned long long d;
    asm("fma.rn.f32x2 %0, %1, %2, %3;" : "=l"(d) : "l"(a), "l"(b), "l"(c));
    return d;
}
__device__ __forceinline__ unsigned long long fadd2(unsigned long long a,
                                                    unsigned long long b) {
    unsigned long long d;
    asm("add.rn.f32x2 %0, %1, %2;" : "=l"(d) : "l"(a), "l"(b));
    return d;
}

// ---------------------------------------------------------------------------
// Kernel 1: fp32 GEMM  C[M,N] = A[M,K] * B[N,K]^T  via packed f32x2 FMA.
// 128x128 CTA tile, BK=16, 256 threads, 8x8 per-thread microtile.
// A operand read from SMEM directly as packed row-pair u64 (zero pack cost);
// B broadcast-packed on the alu pipe (overlaps fma).
// 64 B SMEM per 64 MACs -> crossbar ceiling 256 MAC/cyc/SM; FMA2 ceiling 128
// -> fma-bound. Double-buffered SMEM with register prefetch; 1 bar per K-tile.
// ---------------------------------------------------------------------------
#define BM 128
#define BN 128
#define BK 16

__global__ __launch_bounds__(256)
void gemm_f32x2_nt(const float* __restrict__ A, const float* __restrict__ Bm,
                   float* __restrict__ C)
{
    __shared__ float As[2][BK][BM + 4];
    __shared__ float Bs[2][BK][BN + 4];

    const int tid = threadIdx.x;
    const int tx = tid & 15;          // 0..15 -> N microtile (8 cols)
    const int ty = tid >> 4;          // 0..15 -> M microtile (8 rows)
    const int bm = blockIdx.y * BM;
    const int bn = blockIdx.x * BN;

    const float* Ab = A + (size_t)bm * NIN;
    const float* Bb = Bm + (size_t)bn * NIN;

    // Global->SMEM mapping: each 128x16 tile = 2 float4 per thread.
    const int lrow = tid >> 2;            // 0..63
    const int lcol = (tid & 3) << 2;      // 0,4,8,12

    unsigned long long acc[4][8];         // [row-pair][col]
#pragma unroll
    for (int i = 0; i < 4; i++)
#pragma unroll
        for (int j = 0; j < 8; j++) acc[i][j] = 0ull;

    // Prologue: load K-tile 0 into buffer 0.
    float4 pa0 = *(const float4*)(Ab + (size_t)lrow * NIN + lcol);
    float4 pa1 = *(const float4*)(Ab + (size_t)(lrow + 64) * NIN + lcol);
    float4 pb0 = *(const float4*)(Bb + (size_t)lrow * NIN + lcol);
    float4 pb1 = *(const float4*)(Bb + (size_t)(lrow + 64) * NIN + lcol);
#pragma unroll
    for (int v = 0; v < 4; v++) {
        As[0][lcol + v][lrow]      = (&pa0.x)[v];
        As[0][lcol + v][lrow + 64] = (&pa1.x)[v];
        Bs[0][lcol + v][lrow]      = (&pb0.x)[v];
        Bs[0][lcol + v][lrow + 64] = (&pb1.x)[v];
    }
    __syncthreads();

    const int NT = NIN / BK;   // 128
    for (int t = 0; t < NT; t++) {
        const int p = t & 1;
        // Prefetch next K-tile into registers (overlaps with compute).
        if (t + 1 < NT) {
            const int ko = (t + 1) * BK;
            pa0 = *(const float4*)(Ab + (size_t)lrow * NIN + ko + lcol);
            pa1 = *(const float4*)(Ab + (size_t)(lrow + 64) * NIN + ko + lcol);
            pb0 = *(const float4*)(Bb + (size_t)lrow * NIN + ko + lcol);
            pb1 = *(const float4*)(Bb + (size_t)(lrow + 64) * NIN + ko + lcol);
        }

#pragma unroll
        for (int k = 0; k < BK; k++) {
            // A: two float4 = four packed row-pair u64 (pure reinterpret).
            ulonglong2 a01 = *(const ulonglong2*)&As[p][k][ty * 8];
            ulonglong2 a23 = *(const ulonglong2*)&As[p][k][ty * 8 + 4];
            float4 vb0 = *(const float4*)&Bs[p][k][tx * 8];
            float4 vb1 = *(const float4*)&Bs[p][k][tx * 8 + 4];

            unsigned long long a2[4];
            a2[0] = a01.x; a2[1] = a01.y; a2[2] = a23.x; a2[3] = a23.y;
            unsigned long long b2[8];
            b2[0] = pack2(vb0.x, vb0.x); b2[1] = pack2(vb0.y, vb0.y);
            b2[2] = pack2(vb0.z, vb0.z); b2[3] = pack2(vb0.w, vb0.w);
            b2[4] = pack2(vb1.x, vb1.x); b2[5] = pack2(vb1.y, vb1.y);
            b2[6] = pack2(vb1.z, vb1.z); b2[7] = pack2(vb1.w, vb1.w);
#pragma unroll
            for (int i = 0; i < 4; i++)
#pragma unroll
                for (int j = 0; j < 8; j++)
                    acc[i][j] = ffma2(a2[i], b2[j], acc[i][j]);
        }

        if (t + 1 < NT) {
            const int q = p ^ 1;
#pragma unroll
            for (int v = 0; v < 4; v++) {
                As[q][lcol + v][lrow]      = (&pa0.x)[v];
                As[q][lcol + v][lrow + 64] = (&pa1.x)[v];
                Bs[q][lcol + v][lrow]      = (&pb0.x)[v];
                Bs[q][lcol + v][lrow + 64] = (&pb1.x)[v];
            }
            __syncthreads();
        }
    }

    // Epilogue: unpack row-pairs; each row stores 8 floats as 2x float4.
#pragma unroll
    for (int i = 0; i < 4; i++) {
        float r0[8], r1[8];
#pragma unroll
        for (int j = 0; j < 8; j++) unpack2(acc[i][j], r0[j], r1[j]);
        const size_t rowA = (size_t)(bm + ty * 8 + 2 * i) * NOUT + bn + tx * 8;
        *(float4*)&C[rowA]            = *(float4*)&r0[0];
        *(float4*)&C[rowA + 4]        = *(float4*)&r0[4];
        *(float4*)&C[rowA + NOUT]     = *(float4*)&r1[0];
        *(float4*)&C[rowA + NOUT + 4] = *(float4*)&r1[4];
    }
}

// ---------------------------------------------------------------------------
// Kernel 2: full SNN recurrence. One CTA per batch row; 256 threads.
// Each thread owns 8 neurons (j = tid + 256*i). W_dec held in REGISTERS
// (40 packed f32x2 per thread). Decoder partials via f32x2 FMA; reduction
// via 64-bit shuffles + add.f32x2.
// ---------------------------------------------------------------------------
__global__ __launch_bounds__(256)
void snn_steps(const float* __restrict__ h, const float* __restrict__ Wdec,
               const float* __restrict__ yoh, float* __restrict__ out,
               float* __restrict__ lossPartial)
{
    __shared__ float red[8 * NC + NC];   // per-warp partials + final scratch

    const int b = blockIdx.x;
    const int tid = threadIdx.x;
    const int warp = tid >> 5, lane = tid & 31;

    // Load decoder weights into registers, packed by class pair:
    // w2[i][c] = { Wdec[2c][j], Wdec[2c+1][j] },  j = tid + 256*i
    unsigned long long w2[8][5];
#pragma unroll
    for (int i = 0; i < 8; i++) {
        const int j = tid + 256 * i;
#pragma unroll
        for (int c = 0; c < 5; c++)
            w2[i][c] = pack2(Wdec[(2 * c) * NOUT + j],
                             Wdec[(2 * c + 1) * NOUT + j]);
    }

    float hreg[8], mem[8], spk[8];
#pragma unroll
    for (int i = 0; i < 8; i++) {
        hreg[i] = h[(size_t)b * NOUT + tid + 256 * i];
        mem[i] = 0.0f; spk[i] = 0.0f;
    }

    float ym = 0.0f, ys = 0.0f, yo = 0.0f, lossc = 0.0f;
    if (tid < NC) yo = yoh[b * NC + tid];
    __syncthreads();

    for (int t = 0; t < TSTEPS; t++) {
        unsigned long long acc2[5];
#pragma unroll
        for (int c = 0; c < 5; c++) acc2[c] = 0ull;

#pragma unroll
        for (int i = 0; i < 8; i++) {
            mem[i] = mem[i] * DECAY + hreg[i] - spk[i] * TD;
            spk[i] = (mem[i] > THRESH) ? 1.0f : 0.0f;
            const int j = tid + 256 * i;
            out[(size_t)t * (B_SZ * NOUT) + (size_t)b * NOUT + j] = spk[i];
            const unsigned long long s2 = pack2(spk[i], spk[i]);
#pragma unroll
            for (int c = 0; c < 5; c++)
                acc2[c] = ffma2(s2, w2[i][c], acc2[c]);
        }

        // intra-warp tree reduction on packed pairs
#pragma unroll
        for (int c = 0; c < 5; c++) {
#pragma unroll
            for (int o = 16; o > 0; o >>= 1) {
                unsigned long long other =
                    __shfl_down_sync(0xffffffffu, acc2[c], o);
                acc2[c] = fadd2(acc2[c], other);
            }
        }
        if (lane == 0) {
#pragma unroll
            for (int c = 0; c < 5; c++) {
                float lo, hi;
                unpack2(acc2[c], lo, hi);
                red[warp * NC + 2 * c]     = lo;
                red[warp * NC + 2 * c + 1] = hi;
            }
        }
        __syncthreads();

        if (tid < NC) {
            float tot = 0.0f;
#pragma unroll
            for (int w = 0; w < 8; w++) tot += red[w * NC + tid];
            ym = ym * DECAY + tot - ys * TD;
            ys = (ym > THRESH) ? 1.0f : 0.0f;
            const float d = ys - yo;
            lossc = fmaf(d, d, lossc);
        }
        __syncthreads();   // protect red before next step reuses it
    }

    if (tid < NC) red[8 * NC + tid] = lossc;
    __syncthreads();
    if (tid == 0) {
        float s = 0.0f;
#pragma unroll
        for (int c = 0; c < NC; c++) s += red[8 * NC + c];
        lossPartial[b] = s;
    }
}

// ---------------------------------------------------------------------------
// Kernel 3: reduce per-row loss partials -> out[out_size-1]
// ---------------------------------------------------------------------------
__global__ void loss_reduce(const float* __restrict__ lp, float* __restrict__ out,
                            int out_size)
{
    __shared__ float s[256];
    float v = 0.0f;
    for (int i = threadIdx.x; i < B_SZ; i += 256) v += lp[i];
    s[threadIdx.x] = v;
    __syncthreads();
    for (int o = 128; o > 0; o >>= 1) {
        if (threadIdx.x < o) s[threadIdx.x] += s[threadIdx.x + o];
        __syncthreads();
    }
    if (threadIdx.x == 0)
        out[out_size - 1] = s[0] / (float)(B_SZ * NC);  // mean over [B, NC], summed over T
}

// ---------------------------------------------------------------------------
extern "C" void kernel_launch(void* const* d_in, const int* in_sizes, int n_in,
                              void* d_out, int out_size)
{
    const float* x     = (const float*)d_in[0];   // [1024, 2048]
    const float* W_enc = (const float*)d_in[1];   // [2048, 2048]
    const float* W_dec = (const float*)d_in[2];   // [10, 2048]
    const float* y_oh  = (const float*)d_in[3];   // [1024, 10]
    float* out = (float*)d_out;

    float* h;
    cudaGetSymbolAddress((void**)&h, g_h);
    float* lp;
    cudaGetSymbolAddress((void**)&lp, g_lossPartial);

    // GEMM: h = x @ W_enc^T   (grid = 16 x 8 = 128 CTAs)
    dim3 ggrid(NOUT / BN, B_SZ / BM);
    gemm_f32x2_nt<<<ggrid, 256>>>(x, W_enc, h);

    // Recurrence
    snn_steps<<<B_SZ, 256>>>(h, W_dec, y_oh, out, lp);

    // Final loss scalar
    loss_reduce<<<1, 256>>>(lp, out, out_size);
}